// round 7
// baseline (speedup 1.0000x reference)
#include <cuda_runtime.h>

// Problem constants (fixed shapes per reference)
#define B_    4
#define M_    1024
#define N_    1024
#define DX_   32
#define H_    32
#define DV_   64
#define NPAIR 16      // H_/2 pair-sums per row

#define XLA_TANH_CLAMP 7.99881172180175781f

typedef unsigned long long ull;

// Scratch (no cudaMalloc allowed)
__device__ __align__(16) float g_k2 [B_ * N_ * NPAIR];  // pair sums of k
__device__ __align__(16) float g_q2n[B_ * M_ * NPAIR];  // NEGATED pair sums of q
__device__ __align__(16) float g_kf [B_ * N_ * H_];     // full k projection
__device__ __align__(16) float g_qfn[B_ * M_ * H_];     // NEGATED full q projection
__device__ __align__(16) float g_Sp [B_ * 8 * DV_];     // partial sums of r over n

// ---------------------------------------------------------------------------
// XLA EmitFastTanh (f32, with_fma=true) — bit-faithful replica.
// ---------------------------------------------------------------------------
__device__ __forceinline__ float xla_fast_tanh(float x) {
    float xc = fminf(fmaxf(x, -XLA_TANH_CLAMP), XLA_TANH_CLAMP);
    float x2 = xc * xc;
    float p = fmaf(x2, -2.76076847742355e-16f, 2.00018790482477e-13f);
    p = fmaf(x2, p, -8.60467152213735e-11f);
    p = fmaf(x2, p, 5.12229709037114e-08f);
    p = fmaf(x2, p, 1.48572235717979e-05f);
    p = fmaf(x2, p, 6.37261928875436e-04f);
    p = fmaf(x2, p, 4.89352455891786e-03f);
    p = xc * p;
    float q = fmaf(x2, 1.19825839466702e-06f, 1.18534705686654e-04f);
    q = fmaf(x2, q, 2.26843463243900e-03f);
    q = fmaf(x2, q, 4.89352518554385e-03f);
    float t = p / q;                  // IEEE div.rn
    if (fabsf(x) < 0.0004f) t = x;
    return t;
}

// Packed f32x2 helpers (operands stay in registers; no address-taking)
__device__ __forceinline__ ull add2(ull a, ull b) {
    ull d;
    asm("add.rn.f32x2 %0, %1, %2;" : "=l"(d) : "l"(a), "l"(b));
    return d;
}
__device__ __forceinline__ float hsum2(ull a) {
    float lo, hi;
    asm("mov.b64 {%0, %1}, %2;" : "=f"(lo), "=f"(hi) : "l"(a));
    return lo + hi;
}
#define ABS2_MASK 0x7FFFFFFF7FFFFFFFULL

// ---------------------------------------------------------------------------
// prep: 160 blocks x 256 threads. (unchanged from R6 — outputs bit-identical)
//  blocks   0..127 : projections. 64 rows/block, 4 threads/row, 8 h each.
//                    rows 0..4095 = k (x1), 4096..8191 = q NEGATED (x2).
//  blocks 128..159 : r column-sum partials (8 per batch) -> g_Sp
// ---------------------------------------------------------------------------
__global__ __launch_bounds__(256) void prep_kernel(
    const float* __restrict__ x1,
    const float* __restrict__ x2,
    const float* __restrict__ r_in,
    const float* __restrict__ W,
    const float* __restrict__ bias
) {
    int blk = blockIdx.x, tid = threadIdx.x;

    if (blk >= 128) {
        __shared__ float ps[4][DV_];
        int idx = blk - 128, batch = idx >> 3, part = idx & 7;
        int v = tid & 63, sub = tid >> 6;
        const float* rp = r_in + ((size_t)batch * N_ + part * 128 + sub * 32) * DV_ + v;
        float s = 0.f;
        #pragma unroll
        for (int n = 0; n < 32; n++) s += rp[n * DV_];
        ps[sub][v] = s;
        __syncthreads();
        if (tid < DV_)
            g_Sp[((size_t)batch * 8 + part) * DV_ + tid] =
                (ps[0][tid] + ps[1][tid]) + (ps[2][tid] + ps[3][tid]);
        return;
    }

    __shared__ float Ws[H_][DX_ + 1];
    __shared__ float bs[H_];

    for (int i = tid; i < H_ * DX_; i += 256) {
        int h = i >> 5, d = i & 31;
        Ws[h][d] = W[i];
    }
    if (tid < H_) bs[tid] = bias[tid];
    __syncthreads();

    int row  = blk * 64 + (tid >> 2);
    int quad = tid & 3;
    int isq  = row >= 4096;
    int lrow = row - (isq ? 4096 : 0);
    const float* x = (isq ? x2 : x1) + (size_t)lrow * DX_;
    float sgn = isq ? -1.f : 1.f;

    float xr[DX_];
    {
        const float4* xg = (const float4*)x;
        #pragma unroll
        for (int i = 0; i < DX_ / 4; i++) {
            float4 v = xg[i];
            xr[4*i+0] = v.x; xr[4*i+1] = v.y; xr[4*i+2] = v.z; xr[4*i+3] = v.w;
        }
    }

    float acc[8];
    #pragma unroll
    for (int jj = 0; jj < 8; jj++) {
        int h = quad * 8 + jj;
        float a = bs[h];
        #pragma unroll
        for (int d = 0; d < DX_; d++) a = fmaf(xr[d], Ws[h][d], a);
        acc[jj] = sgn * a;
    }

    {
        float4* of = (float4*)((isq ? g_qfn : g_kf) + (size_t)lrow * H_ + quad * 8);
        of[0] = make_float4(acc[0], acc[1], acc[2], acc[3]);
        of[1] = make_float4(acc[4], acc[5], acc[6], acc[7]);
    }
    {
        float4* op = (float4*)((isq ? g_q2n : g_k2) + (size_t)lrow * NPAIR + quad * 4);
        op[0] = make_float4(acc[0] + acc[1], acc[2] + acc[3],
                            acc[4] + acc[5], acc[6] + acc[7]);
    }
}

// ---------------------------------------------------------------------------
// Cold path (deferred): exact s from stored projections, correction only if
// truly below clamp (delta == 0 otherwise by XLA clamp semantics).
// ---------------------------------------------------------------------------
__device__ __noinline__ void fix_pair(
    float* corr_row, const float* __restrict__ r_in,
    int batch, int m, int n, float w_sat
) {
    const float4* kp = (const float4*)(g_kf  + ((size_t)batch * N_ + n) * H_);
    const float4* qp = (const float4*)(g_qfn + ((size_t)batch * M_ + m) * H_);
    float s = 0.f;
    #pragma unroll
    for (int i = 0; i < H_ / 4; i++) {
        float4 a = kp[i], b = qp[i];   // b is already -q
        s += fabsf(a.x + b.x) + fabsf(a.y + b.y)
           + fabsf(a.z + b.z) + fabsf(a.w + b.w);
    }
    if (s < XLA_TANH_CLAMP) {
        float wv = 1.0f + xla_fast_tanh(-s);
        float delta = wv - w_sat;
        if (delta != 0.f) {
            const float* rp = r_in + ((size_t)batch * N_ + n) * DV_;
            for (int v = 0; v < DV_; v++) atomicAdd(&corr_row[v], delta * rp[v]);
        }
    }
}

// ---------------------------------------------------------------------------
// attn: grid 512 = B x (M/8), 128 threads = 4 warps x 2 m-rows.
// Double-buffered k2 staging (1 sync/chunk). Pair-sum lower bound via packed
// f32x2; bound >= clamp ==> w == w_sat exactly. Flags handled after mainloop.
// ---------------------------------------------------------------------------
#define TM 8
#define NB 64
#define NCHUNK (N_ / NB)

__global__ __launch_bounds__(128, 6) void attn_kernel(
    const float* __restrict__ r_in,
    float* __restrict__ out
) {
    __shared__ ulonglong2 ks[2][4][NB];   // double-buffered [vec][n] k2 chunk
    __shared__ float corr[TM][DV_];
    __shared__ float Ssm[DV_];

    int tid   = threadIdx.x;
    int warp  = tid >> 5;
    int lane  = tid & 31;
    int batch = blockIdx.x >> 7;        // 128 m-tiles per batch
    int mtile = blockIdx.x & 127;
    int m0    = mtile * TM + warp * 2;

    const float w_sat = 1.0f + xla_fast_tanh(-XLA_TANH_CLAMP);

    for (int i = tid; i < TM * DV_; i += 128) ((float*)corr)[i] = 0.f;

    // S[v] = sum of 8 partials (once per block)
    if (tid < DV_) {
        const float* Sp = g_Sp + (size_t)batch * 8 * DV_;
        float S = 0.f;
        #pragma unroll
        for (int p = 0; p < 8; p++) S += Sp[p * DV_ + tid];
        Ssm[tid] = S;
    }

    // negated q pair-sums for both rows (8 ull each)
    ull nq0[8], nq1[8];
    {
        const ull* q0 = (const ull*)(g_q2n + ((size_t)batch * M_ + m0) * NPAIR);
        const ull* q1 = (const ull*)(g_q2n + ((size_t)batch * M_ + m0 + 1) * NPAIR);
        #pragma unroll
        for (int i = 0; i < 8; i++) { nq0[i] = q0[i]; nq1[i] = q1[i]; }
    }

    const ulonglong2* kg = (const ulonglong2*)(g_k2 + (size_t)batch * N_ * NPAIR);

    // staging: chunk = NB*4 = 256 vec slots, 2 per thread
    int nA = tid >> 2,         vA = tid & 3;
    int nB_ = (tid + 128) >> 2, vB = tid & 3;
    ulonglong2 pfA = kg[(size_t)nA * 4 + vA];
    ulonglong2 pfB = kg[(size_t)nB_ * 4 + vB];

    unsigned mask0 = 0, mask1 = 0;

    #pragma unroll 1
    for (int c = 0; c < NCHUNK; c++) {
        int buf = c & 1;
        ks[buf][vA][nA]  = pfA;
        ks[buf][vB][nB_] = pfB;
        __syncthreads();                     // chunk c visible; compute(c-1) done by all
        if (c + 1 < NCHUNK) {
            size_t base = (size_t)(c + 1) * NB * 4;
            pfA = kg[base + (size_t)nA * 4 + vA];
            pfB = kg[base + (size_t)nB_ * 4 + vB];
        }

        #pragma unroll
        for (int ns = 0; ns < NB / 32; ns++) {
            int nl = ns * 32 + lane;
            ull a0 = 0, a1 = 0, b0 = 0, b1 = 0;
            #pragma unroll
            for (int v = 0; v < 4; v++) {
                ulonglong2 kv = ks[buf][v][nl];
                ull d;
                d = add2(kv.x, nq0[2*v+0]) & ABS2_MASK; a0 = add2(a0, d);
                d = add2(kv.y, nq0[2*v+1]) & ABS2_MASK; a1 = add2(a1, d);
                d = add2(kv.x, nq1[2*v+0]) & ABS2_MASK; b0 = add2(b0, d);
                d = add2(kv.y, nq1[2*v+1]) & ABS2_MASK; b1 = add2(b1, d);
            }
            float s0 = hsum2(add2(a0, a1));
            float s1 = hsum2(add2(b0, b1));
            int g = c * (NB / 32) + ns;          // 0..31
            if (s0 < XLA_TANH_CLAMP) mask0 |= 1u << g;
            if (s1 < XLA_TANH_CLAMP) mask1 |= 1u << g;
        }
    }

    // Deferred rare path (cheap: reads stored projections)
    while (mask0) {
        int g = __ffs(mask0) - 1; mask0 &= mask0 - 1;
        int n = (g >> 1) * NB + (g & 1) * 32 + lane;
        fix_pair(corr[warp * 2 + 0], r_in, batch, m0, n, w_sat);
    }
    while (mask1) {
        int g = __ffs(mask1) - 1; mask1 &= mask1 - 1;
        int n = (g >> 1) * NB + (g & 1) * 32 + lane;
        fix_pair(corr[warp * 2 + 1], r_in, batch, m0 + 1, n, w_sat);
    }
    __syncthreads();

    // out[m][v] = w_sat * S[v] + corr[m][v]
    float* op = out + ((size_t)batch * M_ + mtile * TM) * DV_;
    for (int i = tid; i < TM * DV_; i += 128) {
        int ml = i >> 6, v = i & 63;
        op[(size_t)ml * DV_ + v] = fmaf(w_sat, Ssm[v], corr[ml][v]);
    }
}

// ---------------------------------------------------------------------------
// Launch: bind inputs by element count (robust to metadata ordering).
// ---------------------------------------------------------------------------
extern "C" void kernel_launch(void* const* d_in, const int* in_sizes, int n_in,
                              void* d_out, int out_size) {
    const float* x1 = nullptr;
    const float* x2 = nullptr;
    const float* r  = nullptr;
    const float* W  = nullptr;
    const float* b  = nullptr;

    for (int i = 0; i < n_in; i++) {
        int sz = in_sizes[i];
        const float* p = (const float*)d_in[i];
        if (sz == B_ * N_ * DV_)      { r = p; }
        else if (sz == H_ * DX_)      { W = p; }
        else if (sz == H_)            { b = p; }
        else if (sz == B_ * N_ * DX_) { if (!x1) x1 = p; else x2 = p; }
    }
    if (!x1 || !x2 || !r || !W || !b) {
        x1 = (const float*)d_in[0];
        x2 = (const float*)d_in[1];
        r  = (const float*)d_in[2];
        W  = (const float*)d_in[3];
        b  = (const float*)d_in[4];
    }

    float* out = (float*)d_out;
    (void)out_size;

    prep_kernel<<<160, 256>>>(x1, x2, r, W, b);      // kf, qfn, k2, q2n, Sp
    attn_kernel<<<B_ * (M_ / TM), 128>>>(r, out);
}

// round 8
// speedup vs baseline: 1.0028x; 1.0028x over previous
#include <cuda_runtime.h>

// Problem constants (fixed shapes per reference)
#define B_    4
#define M_    1024
#define N_    1024
#define DX_   32
#define H_    32
#define DV_   64
#define NPAIR 16      // H_/2 pair-sums per row

#define XLA_TANH_CLAMP 7.99881172180175781f

typedef unsigned long long ull;

// Scratch (no cudaMalloc allowed)
__device__ __align__(16) ull   g_k2t[B_ * 8 * N_];      // TRANSPOSED k pair-sums: [b][i][n], i=pair-pair
__device__ __align__(16) float g_q2n[B_ * M_ * NPAIR];  // NEGATED pair sums of q (row-major)
__device__ __align__(16) float g_kf [B_ * N_ * H_];     // full k projection
__device__ __align__(16) float g_qfn[B_ * M_ * H_];     // NEGATED full q projection
__device__ __align__(16) float g_Sp [B_ * 8 * DV_];     // partial sums of r over n

// ---------------------------------------------------------------------------
// XLA EmitFastTanh (f32, with_fma=true) — bit-faithful replica.
// ---------------------------------------------------------------------------
__device__ __forceinline__ float xla_fast_tanh(float x) {
    float xc = fminf(fmaxf(x, -XLA_TANH_CLAMP), XLA_TANH_CLAMP);
    float x2 = xc * xc;
    float p = fmaf(x2, -2.76076847742355e-16f, 2.00018790482477e-13f);
    p = fmaf(x2, p, -8.60467152213735e-11f);
    p = fmaf(x2, p, 5.12229709037114e-08f);
    p = fmaf(x2, p, 1.48572235717979e-05f);
    p = fmaf(x2, p, 6.37261928875436e-04f);
    p = fmaf(x2, p, 4.89352455891786e-03f);
    p = xc * p;
    float q = fmaf(x2, 1.19825839466702e-06f, 1.18534705686654e-04f);
    q = fmaf(x2, q, 2.26843463243900e-03f);
    q = fmaf(x2, q, 4.89352518554385e-03f);
    float t = p / q;                  // IEEE div.rn
    if (fabsf(x) < 0.0004f) t = x;
    return t;
}

// Packed f32x2 helpers
__device__ __forceinline__ ull add2(ull a, ull b) {
    ull d;
    asm("add.rn.f32x2 %0, %1, %2;" : "=l"(d) : "l"(a), "l"(b));
    return d;
}
__device__ __forceinline__ float hsum2(ull a) {
    float lo, hi;
    asm("mov.b64 {%0, %1}, %2;" : "=f"(lo), "=f"(hi) : "l"(a));
    return lo + hi;
}
__device__ __forceinline__ ull pk2(float lo, float hi) {
    ull r;
    asm("mov.b64 %0, {%1, %2};" : "=l"(r) : "f"(lo), "f"(hi));
    return r;
}
#define ABS2_MASK 0x7FFFFFFF7FFFFFFFULL

// ---------------------------------------------------------------------------
// prep: 160 blocks x 256 threads.
//  blocks   0..127 : projections. 64 rows/block, 4 threads/row, 8 h each.
//                    rows 0..4095 = k (x1) -> g_kf + g_k2t (transposed),
//                    rows 4096..8191 = q NEGATED (x2) -> g_qfn + g_q2n.
//  blocks 128..159 : r column-sum partials (8 per batch) -> g_Sp
// ---------------------------------------------------------------------------
__global__ __launch_bounds__(256) void prep_kernel(
    const float* __restrict__ x1,
    const float* __restrict__ x2,
    const float* __restrict__ r_in,
    const float* __restrict__ W,
    const float* __restrict__ bias
) {
    int blk = blockIdx.x, tid = threadIdx.x;

    if (blk >= 128) {
        __shared__ float ps[4][DV_];
        int idx = blk - 128, batch = idx >> 3, part = idx & 7;
        int v = tid & 63, sub = tid >> 6;
        const float* rp = r_in + ((size_t)batch * N_ + part * 128 + sub * 32) * DV_ + v;
        float s = 0.f;
        #pragma unroll
        for (int n = 0; n < 32; n++) s += rp[n * DV_];
        ps[sub][v] = s;
        __syncthreads();
        if (tid < DV_)
            g_Sp[((size_t)batch * 8 + part) * DV_ + tid] =
                (ps[0][tid] + ps[1][tid]) + (ps[2][tid] + ps[3][tid]);
        return;
    }

    __shared__ float Ws[H_][DX_ + 1];
    __shared__ float bs[H_];

    for (int i = tid; i < H_ * DX_; i += 256) {
        int h = i >> 5, d = i & 31;
        Ws[h][d] = W[i];
    }
    if (tid < H_) bs[tid] = bias[tid];
    __syncthreads();

    int row  = blk * 64 + (tid >> 2);    // 0..8191
    int quad = tid & 3;                  // h = quad*8 .. quad*8+7
    int isq  = row >= 4096;
    int lrow = row - (isq ? 4096 : 0);
    const float* x = (isq ? x2 : x1) + (size_t)lrow * DX_;
    float sgn = isq ? -1.f : 1.f;

    float xr[DX_];
    {
        const float4* xg = (const float4*)x;
        #pragma unroll
        for (int i = 0; i < DX_ / 4; i++) {
            float4 v = xg[i];
            xr[4*i+0] = v.x; xr[4*i+1] = v.y; xr[4*i+2] = v.z; xr[4*i+3] = v.w;
        }
    }

    float acc[8];
    #pragma unroll
    for (int jj = 0; jj < 8; jj++) {
        int h = quad * 8 + jj;
        float a = bs[h];
        #pragma unroll
        for (int d = 0; d < DX_; d++) a = fmaf(xr[d], Ws[h][d], a);
        acc[jj] = sgn * a;
    }

    // full projection (signed)
    {
        float4* of = (float4*)((isq ? g_qfn : g_kf) + (size_t)lrow * H_ + quad * 8);
        of[0] = make_float4(acc[0], acc[1], acc[2], acc[3]);
        of[1] = make_float4(acc[4], acc[5], acc[6], acc[7]);
    }
    // pair sums
    float p0 = acc[0] + acc[1], p1 = acc[2] + acc[3];
    float p2 = acc[4] + acc[5], p3 = acc[6] + acc[7];
    if (isq) {
        // q: row-major [M][16] floats (read as broadcast per warp)
        float4* op = (float4*)(g_q2n + (size_t)lrow * NPAIR + quad * 4);
        op[0] = make_float4(p0, p1, p2, p3);
    } else {
        // k: transposed [b][i][n] ull (i = pair-pair index), coalesced reads in attn
        int batch = lrow >> 10, n = lrow & (N_ - 1);
        g_k2t[((size_t)batch * 8 + quad * 2 + 0) * N_ + n] = pk2(p0, p1);
        g_k2t[((size_t)batch * 8 + quad * 2 + 1) * N_ + n] = pk2(p2, p3);
    }
}

// ---------------------------------------------------------------------------
// fill: out[b][m][v] = w_sat * S[b][v]   (base value; corrections added
// atomically by attn afterwards — stream order guarantees safety).
// 64 blocks x 256 threads; block = (batch, 64-row group).
// ---------------------------------------------------------------------------
__global__ __launch_bounds__(256) void fill_kernel(float* __restrict__ out) {
    __shared__ float Ssm[DV_];
    int blk = blockIdx.x, tid = threadIdx.x;
    int batch = blk >> 4, grp = blk & 15;

    const float w_sat = 1.0f + xla_fast_tanh(-XLA_TANH_CLAMP);

    if (tid < DV_) {
        const float* Sp = g_Sp + (size_t)batch * 8 * DV_;
        float S = 0.f;
        #pragma unroll
        for (int p = 0; p < 8; p++) S += Sp[p * DV_ + tid];
        Ssm[tid] = w_sat * S;
    }
    __syncthreads();

    // 64 rows x 64 v = 1024 float4; 4 per thread
    float4* op = (float4*)(out + ((size_t)batch * M_ + grp * 64) * DV_);
    #pragma unroll
    for (int i = 0; i < 4; i++) {
        int idx = tid + i * 256;
        int v4 = idx & 15;
        op[idx] = make_float4(Ssm[4*v4+0], Ssm[4*v4+1], Ssm[4*v4+2], Ssm[4*v4+3]);
    }
}

// ---------------------------------------------------------------------------
// Cold path (deferred): exact s from stored projections; atomic correction
// into out only if truly below clamp (delta == 0 otherwise).
// ---------------------------------------------------------------------------
__device__ __noinline__ void fix_pair(
    float* __restrict__ out_row, const float* __restrict__ r_in,
    int batch, int m, int n, float w_sat
) {
    const float4* kp = (const float4*)(g_kf  + ((size_t)batch * N_ + n) * H_);
    const float4* qp = (const float4*)(g_qfn + ((size_t)batch * M_ + m) * H_);
    float s = 0.f;
    #pragma unroll
    for (int i = 0; i < H_ / 4; i++) {
        float4 a = kp[i], b = qp[i];   // b is already -q
        s += fabsf(a.x + b.x) + fabsf(a.y + b.y)
           + fabsf(a.z + b.z) + fabsf(a.w + b.w);
    }
    if (s < XLA_TANH_CLAMP) {
        float wv = 1.0f + xla_fast_tanh(-s);
        float delta = wv - w_sat;
        if (delta != 0.f) {
            const float* rp = r_in + ((size_t)batch * N_ + n) * DV_;
            for (int v = 0; v < DV_; v++) atomicAdd(&out_row[v], delta * rp[v]);
        }
    }
}

// ---------------------------------------------------------------------------
// attn: grid 2048 = B x (M/8) x 4 n-slices. 128 threads = 4 warps x 2 m-rows.
// No shared memory, no syncs: each lane reads its own n's k2 data via
// coalesced LDG.64 from the transposed layout. Pair-sum lower bound >= clamp
// ==> w == w_sat exactly (XLA clamp). Rare flags fixed after the mainloop
// with atomics into out.
// ---------------------------------------------------------------------------
#define TM      8
#define NSLICE  4
#define NSEG    (N_ / NSLICE)       // 256 n per CTA

__global__ __launch_bounds__(128, 6) void attn_kernel(
    const float* __restrict__ r_in,
    float* __restrict__ out
) {
    int tid   = threadIdx.x;
    int warp  = tid >> 5;
    int lane  = tid & 31;
    int bid   = blockIdx.x;
    int batch = bid >> 9;               // 512 units per batch
    int rem   = bid & 511;
    int mtile = rem >> 2;               // 128 m-tiles
    int slice = rem & 3;
    int m0    = mtile * TM + warp * 2;
    int nbase = slice * NSEG;

    const float w_sat = 1.0f + xla_fast_tanh(-XLA_TANH_CLAMP);

    // negated q pair-sums for both rows (8 ull each; warp-uniform rows)
    ull nq0[8], nq1[8];
    {
        const ull* q0 = (const ull*)(g_q2n + ((size_t)batch * M_ + m0) * NPAIR);
        const ull* q1 = (const ull*)(g_q2n + ((size_t)batch * M_ + m0 + 1) * NPAIR);
        #pragma unroll
        for (int i = 0; i < 8; i++) { nq0[i] = q0[i]; nq1[i] = q1[i]; }
    }

    const ull* kt = g_k2t + (size_t)batch * 8 * N_;   // [i][n]

    unsigned mask0 = 0, mask1 = 0;      // 8 group bits each

    #pragma unroll 1
    for (int g = 0; g < NSEG / 32; g++) {
        int n = nbase + g * 32 + lane;
        ull kv[8];
        #pragma unroll
        for (int i = 0; i < 8; i++) kv[i] = kt[(size_t)i * N_ + n];  // coalesced LDG.64

        ull a0 = 0, a1 = 0, b0 = 0, b1 = 0;
        #pragma unroll
        for (int i = 0; i < 8; i++) {
            ull d0 = add2(kv[i], nq0[i]) & ABS2_MASK;
            ull d1 = add2(kv[i], nq1[i]) & ABS2_MASK;
            if (i & 1) { a1 = add2(a1, d0); b1 = add2(b1, d1); }
            else       { a0 = add2(a0, d0); b0 = add2(b0, d1); }
        }
        float s0 = hsum2(add2(a0, a1));   // lower bound s(m0,   n)
        float s1 = hsum2(add2(b0, b1));   // lower bound s(m0+1, n)
        if (s0 < XLA_TANH_CLAMP) mask0 |= 1u << g;
        if (s1 < XLA_TANH_CLAMP) mask1 |= 1u << g;
    }

    // Deferred rare path: exact recompute + atomic correction into out.
    while (mask0) {
        int g = __ffs(mask0) - 1; mask0 &= mask0 - 1;
        int n = nbase + g * 32 + lane;
        fix_pair(out + ((size_t)batch * M_ + m0) * DV_, r_in, batch, m0, n, w_sat);
    }
    while (mask1) {
        int g = __ffs(mask1) - 1; mask1 &= mask1 - 1;
        int n = nbase + g * 32 + lane;
        fix_pair(out + ((size_t)batch * M_ + m0 + 1) * DV_, r_in, batch, m0 + 1, n, w_sat);
    }
}

// ---------------------------------------------------------------------------
// Launch: bind inputs by element count (robust to metadata ordering).
// ---------------------------------------------------------------------------
extern "C" void kernel_launch(void* const* d_in, const int* in_sizes, int n_in,
                              void* d_out, int out_size) {
    const float* x1 = nullptr;
    const float* x2 = nullptr;
    const float* r  = nullptr;
    const float* W  = nullptr;
    const float* b  = nullptr;

    for (int i = 0; i < n_in; i++) {
        int sz = in_sizes[i];
        const float* p = (const float*)d_in[i];
        if (sz == B_ * N_ * DV_)      { r = p; }
        else if (sz == H_ * DX_)      { W = p; }
        else if (sz == H_)            { b = p; }
        else if (sz == B_ * N_ * DX_) { if (!x1) x1 = p; else x2 = p; }
    }
    if (!x1 || !x2 || !r || !W || !b) {
        x1 = (const float*)d_in[0];
        x2 = (const float*)d_in[1];
        r  = (const float*)d_in[2];
        W  = (const float*)d_in[3];
        b  = (const float*)d_in[4];
    }

    float* out = (float*)d_out;
    (void)out_size;

    prep_kernel<<<160, 256>>>(x1, x2, r, W, b);      // kf, qfn, k2t, q2n, Sp
    fill_kernel<<<64, 256>>>(out);                   // out = w_sat * S
    attn_kernel<<<B_ * (M_ / TM) * NSLICE, 128>>>(r, out);  // rare corrections
}